// round 17
// baseline (speedup 1.0000x reference)
#include <cuda_runtime.h>
#include <cuda_fp16.h>
#include <cstdint>

// Problem dims
#define LSEQ 32768
#define HDIM 256
#define PDIM 128
#define TCH  64                   // scan chunk length
#define NCHUNK (LSEQ / TCH)       // 512

// ---------------------------------------------------------------------------
__device__ __forceinline__ uint32_t smem_u32(const void* p) {
    uint32_t a;
    asm("{ .reg .u64 t; cvta.to.shared.u64 t, %1; cvt.u32.u64 %0, t; }" : "=r"(a) : "l"(p));
    return a;
}
__device__ __forceinline__ void ldsm_x4(uint32_t (&r)[4], uint32_t addr) {
    asm volatile("ldmatrix.sync.aligned.m8n8.x4.shared.b16 {%0,%1,%2,%3}, [%4];"
        : "=r"(r[0]), "=r"(r[1]), "=r"(r[2]), "=r"(r[3]) : "r"(addr));
}
__device__ __forceinline__ void mma_f16(float (&d)[4], const uint32_t (&a)[4],
                                        uint32_t b0, uint32_t b1) {
    asm volatile("mma.sync.aligned.m16n8k16.row.col.f32.f16.f16.f32 "
        "{%0,%1,%2,%3}, {%4,%5,%6,%7}, {%8,%9}, {%0,%1,%2,%3};"
        : "+f"(d[0]), "+f"(d[1]), "+f"(d[2]), "+f"(d[3])
        : "r"(a[0]), "r"(a[1]), "r"(a[2]), "r"(a[3]), "r"(b0), "r"(b1));
}
__device__ __forceinline__ void mma_f16_u4(float (&d)[4], const uint4& a,
                                           uint32_t b0, uint32_t b1) {
    asm volatile("mma.sync.aligned.m16n8k16.row.col.f32.f16.f16.f32 "
        "{%0,%1,%2,%3}, {%4,%5,%6,%7}, {%8,%9}, {%0,%1,%2,%3};"
        : "+f"(d[0]), "+f"(d[1]), "+f"(d[2]), "+f"(d[3])
        : "r"(a.x), "r"(a.y), "r"(a.z), "r"(a.w), "r"(b0), "r"(b1));
}
__device__ __forceinline__ void cp_async16(uint32_t dst, const void* src) {
    asm volatile("cp.async.cg.shared.global [%0], [%1], 16;" :: "r"(dst), "l"(src));
}
#define CP_COMMIT() asm volatile("cp.async.commit_group;")
#define CP_WAIT0()  asm volatile("cp.async.wait_group 0;")

__device__ __forceinline__ uint32_t pack_h2(float lo, float hi) {
    return ((uint32_t)__half_as_ushort(__float2half_rn(hi)) << 16) |
           __half_as_ushort(__float2half_rn(lo));
}

// -------- device scratch (static) ------------------------------------------
__device__ __align__(128) __half g_W1h[256 * 256];  // GEMM1 B (fp16): [n=2p+ri][k=h]
__device__ __align__(128) __half g_W2h[256 * 256];  // GEMM2 B (fp16): [n=h][k=2p+ri]
__device__ float2 g_lam[PDIM];
__device__ float2 g_lamT[PDIM];
__device__ float2 g_lampow[TCH * PDIM];             // lambda^(t+1)
// x_local in fp16 MMA A-fragment layout:
// frag (mt, kt): 32 lanes x uint4; reg j of lane l = half2 at
// row = mt*16 + (l>>2) + 8*(j&1), cols = kt*16 + (l&3)*2 + 8*(j>>1) + {0,1}
__device__ __align__(128) uint4 g_Xfrag[(LSEQ / 16) * 16 * 32];   // 16 MB
__device__ float2 g_carry[NCHUNK * PDIM];
__device__ float2 g_pfx[NCHUNK * PDIM];

// ---------------------------------------------------------------------------
// Prep
// ---------------------------------------------------------------------------
__global__ void prep_kernel(const float* __restrict__ Lre,
                            const float* __restrict__ Lim,
                            const float* __restrict__ B,
                            const float* __restrict__ C,
                            const float* __restrict__ logstep) {
    const int p = blockIdx.x;
    const int h = threadIdx.x;

    const float step = expf(logstep[p]);
    const float lr = Lre[p], li = Lim[p];
    const float ar = lr * step, ai = li * step;

    float s, c;
    const float mag = expf(ar);
    sincosf(ai, &s, &c);
    const float lam_re = mag * c, lam_im = mag * s;

    const float dr = lam_re - 1.0f, di = lam_im;
    const float inv_den = 1.0f / (lr * lr + li * li);
    const float fr = (dr * lr + di * li) * inv_den;
    const float fi = (di * lr - dr * li) * inv_den;

    const float b0 = B[(p * HDIM + h) * 2 + 0];
    const float b1 = B[(p * HDIM + h) * 2 + 1];
    g_W1h[(2 * p + 0) * 256 + h] = __float2half_rn(fr * b0 - fi * b1);
    g_W1h[(2 * p + 1) * 256 + h] = __float2half_rn(fr * b1 + fi * b0);

    g_W2h[h * 256 + 2 * p + 0] = __float2half_rn( 2.0f * C[(h * PDIM + p) * 2 + 0]);
    g_W2h[h * 256 + 2 * p + 1] = __float2half_rn(-2.0f * C[(h * PDIM + p) * 2 + 1]);

    if (h == 0) g_lam[p] = make_float2(lam_re, lam_im);

    if (h < TCH) {
        const float t = (float)(h + 1);
        float ss, cc;
        const float m = expf(ar * t);
        sincosf(ai * t, &ss, &cc);
        float2 pw = make_float2(m * cc, m * ss);
        g_lampow[h * PDIM + p] = pw;
        if (h == TCH - 1) g_lamT[p] = pw;
    }
}

// ---------------------------------------------------------------------------
// GEMM1: CTA 64x128, BK=64, 4 warps (2Mx2N), warp tile 32x64, 128 threads.
// A=u (fp32->fp16 staged in SMEM), B=W1 via cp.async.
// Epilogue: local scan over chunk, then write x_local as fp16 A-fragments.
// ---------------------------------------------------------------------------
#define NTHREADS 128
#define STAGE_SZ 24576               // A 8K | B 16K
#define OFF_A   0
#define OFF_B   8192
#define XS_STRIDE 132                // floats per row in epilogue staging
#define SM_TOTAL1 (2 * STAGE_SZ)     // 49152

__global__ __launch_bounds__(NTHREADS, 4)
void gemm1_kernel(const float* __restrict__ u) {
    extern __shared__ char smem[];
    const uint32_t smem_base = smem_u32(smem);
    const int tid = threadIdx.x;
    const int wid = tid >> 5;
    const int lane = tid & 31;
    const int warp_m = wid >> 1;       // 0..1 (32 rows each)
    const int warp_n = wid & 1;        // 0..1 (64 cols each)
    const int n0 = blockIdx.x * 128;
    const int m0 = blockIdx.y * 64;

    float acc[16][4];
#pragma unroll
    for (int i = 0; i < 16; i++)
#pragma unroll
        for (int j = 0; j < 4; j++) acc[i][j] = 0.0f;

    uint2 aReg2[8];

    auto loadA = [&](int c) {
#pragma unroll
        for (int j = 0; j < 8; j++) {
            const int i4 = tid + j * NTHREADS;   // 1024 float4s (64x64 fp32)
            const int row = i4 >> 4;
            const int fc = (i4 & 15) << 2;
            const float4 v = *reinterpret_cast<const float4*>(
                u + (size_t)(m0 + row) * 256 + c * 64 + fc);
            uint2 hv;
            hv.x = pack_h2(v.x, v.y);
            hv.y = pack_h2(v.z, v.w);
            aReg2[j] = hv;
        }
    };
    auto storeA = [&](int buf) {
#pragma unroll
        for (int j = 0; j < 8; j++) {
            const int i4 = tid + j * NTHREADS;
            const int row = i4 >> 4;
            const int fc = (i4 & 15) << 2;
            const uint32_t off = (uint32_t)(buf * STAGE_SZ + row * 128 +
                                 (((fc >> 3) ^ (row & 7)) << 4) + ((fc & 4) << 1));
            *reinterpret_cast<uint2*>(smem + OFF_A + off) = aReg2[j];
        }
    };
    auto issueB = [&](int c, int buf) {
#pragma unroll
        for (int j = 0; j < 8; j++) {
            const int i = tid + j * NTHREADS;      // 1024 16B units (128x64 fp16)
            const int row = i >> 3;
            const int un = i & 7;
            const uint32_t off = (uint32_t)(buf * STAGE_SZ + row * 128 +
                                 ((un ^ (row & 7)) << 4));
            cp_async16(smem_base + OFF_B + off,
                       g_W1h + (size_t)(n0 + row) * 256 + c * 64 + un * 8);
        }
        CP_COMMIT();
    };
    auto compute = [&](int buf) {
        const uint32_t ab = smem_base + OFF_A + buf * STAGE_SZ;
        const uint32_t bb = smem_base + OFF_B + buf * STAGE_SZ;
        const int arow = (lane & 7) + ((lane >> 3) & 1) * 8;
        const int akc = lane >> 4;
        uint32_t baseA[2], baseB[4];
#pragma unroll
        for (int mi = 0; mi < 2; mi++) {
            const int row = warp_m * 32 + mi * 16 + arow;
            baseA[mi] = (uint32_t)(row * 128 + ((row & 7) << 4));
        }
#pragma unroll
        for (int hg = 0; hg < 4; hg++) {
            const int row = warp_n * 64 + hg * 16 + arow;
            baseB[hg] = (uint32_t)(row * 128 + ((row & 7) << 4));
        }
#pragma unroll
        for (int kk = 0; kk < 4; kk++) {
            const uint32_t kcx = (uint32_t)((kk * 2 + akc) << 4);
            uint32_t af[2][4], bq[4][4];
#pragma unroll
            for (int mi = 0; mi < 2; mi++)
                ldsm_x4(af[mi], ab + (baseA[mi] ^ kcx));
#pragma unroll
            for (int hg = 0; hg < 4; hg++)
                ldsm_x4(bq[hg], bb + (baseB[hg] ^ kcx));
#pragma unroll
            for (int mi = 0; mi < 2; mi++)
#pragma unroll
                for (int ni = 0; ni < 8; ni++) {
                    const int hg = ni >> 1, s2 = ni & 1;
                    mma_f16(acc[mi * 8 + ni], af[mi], bq[hg][s2], bq[hg][s2 + 2]);
                }
        }
    };

    issueB(0, 0);
    loadA(0);
    for (int c = 0; c < 4; c++) {
        const int buf = c & 1;
        storeA(buf);
        CP_WAIT0();
        __syncthreads();
        if (c < 3) {
            issueB(c + 1, buf ^ 1);
            loadA(c + 1);
        }
        compute(buf);
    }
    __syncthreads();   // before SMEM reuse

    // ---- epilogue: stage Bu tile in SMEM, local scan, write fragment layout ----
    float* xs = reinterpret_cast<float*>(smem);
#pragma unroll
    for (int mi = 0; mi < 2; mi++) {
        const int r0 = warp_m * 32 + mi * 16 + (lane >> 2);
#pragma unroll
        for (int ni = 0; ni < 8; ni++) {
            const int cc = warp_n * 64 + ni * 8 + (lane & 3) * 2;
            const float* a = acc[mi * 8 + ni];
            *reinterpret_cast<float2*>(xs + r0 * XS_STRIDE + cc) = make_float2(a[0], a[1]);
            *reinterpret_cast<float2*>(xs + (r0 + 8) * XS_STRIDE + cc) = make_float2(a[2], a[3]);
        }
    }
    __syncthreads();

    if (tid < 64) {
        const int pg = (n0 >> 1) + tid;          // this CTA covers 64 states
        const float2 lam = g_lam[pg];
        float2 x = make_float2(0.0f, 0.0f);
        float* base = xs + 2 * tid;
#pragma unroll 4
        for (int t = 0; t < 64; t++) {
            float2 b = *reinterpret_cast<float2*>(base + t * XS_STRIDE);
            const float nr = lam.x * x.x - lam.y * x.y + b.x;
            const float ni2 = lam.x * x.y + lam.y * x.x + b.y;
            x.x = nr; x.y = ni2;
            *reinterpret_cast<float2*>(base + t * XS_STRIDE) = x;
        }
        g_carry[(m0 >> 6) * 128 + pg] = x;       // one chunk per CTA (BM=64=TCH)
    }
    __syncthreads();

    // fragment-layout store: 32 frags/CTA (4 m-tiles x 8 k-tiles), 8 per warp
#pragma unroll
    for (int j = 0; j < 8; j++) {
        const int f = wid * 8 + j;           // 0..31
        const int mtl = f >> 3;              // 0..3
        const int kt = f & 7;                // 0..7
        const int rl = mtl * 16 + (lane >> 2);
        const int cl = kt * 16 + (lane & 3) * 2;
        const float2 v0 = *reinterpret_cast<const float2*>(xs + rl * XS_STRIDE + cl);
        const float2 v1 = *reinterpret_cast<const float2*>(xs + (rl + 8) * XS_STRIDE + cl);
        const float2 v2 = *reinterpret_cast<const float2*>(xs + rl * XS_STRIDE + cl + 8);
        const float2 v3 = *reinterpret_cast<const float2*>(xs + (rl + 8) * XS_STRIDE + cl + 8);
        uint4 o;
        o.x = pack_h2(v0.x, v0.y);
        o.y = pack_h2(v1.x, v1.y);
        o.z = pack_h2(v2.x, v2.y);
        o.w = pack_h2(v3.x, v3.y);
        const size_t addr = ((size_t)(((m0 >> 4) + mtl) * 16 + (n0 >> 4) + kt)) * 32 + lane;
        g_Xfrag[addr] = o;
    }
}

// ---------------------------------------------------------------------------
// Parallel carry scan across chunks (Kogge-Stone), exclusive prefix -> g_pfx.
// ---------------------------------------------------------------------------
__global__ __launch_bounds__(NCHUNK)
void carry_scan_par_kernel() {
    const int p = blockIdx.x;
    const int j = threadIdx.x;
    __shared__ float2 sa[2][NCHUNK];
    __shared__ float2 sb[2][NCHUNK];

    float2 a = g_lamT[p];
    float2 b = g_carry[j * PDIM + p];
    int cur = 0;
    sa[0][j] = a;
    sb[0][j] = b;
    __syncthreads();

#pragma unroll
    for (int s = 1; s < NCHUNK; s <<= 1) {
        float2 na = a, nb = b;
        if (j >= s) {
            const float2 pa = sa[cur][j - s];
            const float2 pb = sb[cur][j - s];
            na.x = a.x * pa.x - a.y * pa.y;
            na.y = a.x * pa.y + a.y * pa.x;
            nb.x = a.x * pb.x - a.y * pb.y + b.x;
            nb.y = a.x * pb.y + a.y * pb.x + b.y;
        }
        cur ^= 1;
        sa[cur][j] = na;
        sb[cur][j] = nb;
        a = na;
        b = nb;
        __syncthreads();
    }
    g_pfx[j * PDIM + p] = (j == 0) ? make_float2(0.0f, 0.0f) : sb[cur][j - 1];
}

// ---------------------------------------------------------------------------
// In-place fragment fix-up: x += lambda^(tloc+1) * pfx[chunk], per chunk.
// grid = NCHUNK, 256 threads. One read+write pass over g_Xfrag.
// ---------------------------------------------------------------------------
__global__ __launch_bounds__(256)
void fix_frag_kernel() {
    const int chunk = blockIdx.x;
    const int tid = threadIdx.x;
    __shared__ float2 spfx[PDIM];
    if (tid < PDIM) spfx[tid] = g_pfx[chunk * PDIM + tid];
    __syncthreads();

#pragma unroll
    for (int i = 0; i < 8; i++) {
        const int idx = tid + i * 256;        // 0..2047 lane-frags
        const int f = idx >> 5;               // 0..63
        const int lane = idx & 31;
        const int mtl = f >> 4;               // 0..3
        const int kt = f & 15;                // 0..15
        const size_t addr = ((size_t)((chunk * 4 + mtl) * 16 + kt)) * 32 + lane;
        uint4 v = g_Xfrag[addr];
        uint32_t* vp = reinterpret_cast<uint32_t*>(&v);
        const int t0 = mtl * 16 + (lane >> 2);
        const int p0 = kt * 8 + (lane & 3);
        const int ts[4] = {t0, t0 + 8, t0, t0 + 8};
        const int ps[4] = {p0, p0, p0 + 4, p0 + 4};
#pragma unroll
        for (int j = 0; j < 4; j++) {
            const __half2 h = *reinterpret_cast<const __half2*>(&vp[j]);
            float2 x = __half22float2(h);
            const float2 pw = g_lampow[ts[j] * PDIM + ps[j]];
            const float2 cf = spfx[ps[j]];
            x.x += pw.x * cf.x - pw.y * cf.y;
            x.y += pw.x * cf.y + pw.y * cf.x;
            vp[j] = pack_h2(x.x, x.y);
        }
        g_Xfrag[addr] = v;
    }
}

// ---------------------------------------------------------------------------
// GEMM2: CTA 64x128, BK=64, 4 warps (2Mx2N), warp tile 32x64, 128 threads.
// A = fully-fixed x fragments, direct LDG.128 -> MMA regs (no STS/LDSM).
// B = W2 via cp.async + ldmatrix, double-buffered.
// Epilogue: y = acc + D*u.
// ---------------------------------------------------------------------------
#define STAGE2   16384               // B only: 128 rows x 128B
#define SM_TOTAL2 (2 * STAGE2)       // 32768

__global__ __launch_bounds__(NTHREADS, 4)
void gemm2_kernel(const float* __restrict__ u,
                  float* __restrict__ y,
                  const float* __restrict__ Dv) {
    extern __shared__ char smem[];
    const uint32_t smem_base = smem_u32(smem);
    const int tid = threadIdx.x;
    const int wid = tid >> 5;
    const int lane = tid & 31;
    const int warp_m = wid >> 1;       // 0..1 (32 rows each)
    const int warp_n = wid & 1;        // 0..1 (64 cols each)
    const int n0 = blockIdx.x * 128;
    const int m0 = blockIdx.y * 64;

    float acc[16][4];
#pragma unroll
    for (int i = 0; i < 16; i++)
#pragma unroll
        for (int j = 0; j < 4; j++) acc[i][j] = 0.0f;

    auto issueB = [&](int c, int buf) {
#pragma unroll
        for (int j = 0; j < 8; j++) {
            const int i = tid + j * NTHREADS;      // 1024 16B units (128x64 fp16)
            const int row = i >> 3;
            const int un = i & 7;
            const uint32_t off = (uint32_t)(buf * STAGE2 + row * 128 +
                                 ((un ^ (row & 7)) << 4));
            cp_async16(smem_base + off,
                       g_W2h + (size_t)(n0 + row) * 256 + c * 64 + un * 8);
        }
        CP_COMMIT();
    };
    // A-fragment base for this warp: frags (mtg, ktg) with mtg = m0/16+warp_m*2+mi
    const size_t afragBase = ((size_t)(((m0 >> 4) + warp_m * 2) * 16)) * 32 + lane;
    auto ldgA = [&](int c, int kk, uint4 (&a)[2]) {
        const size_t addr = afragBase + (size_t)(c * 4 + kk) * 32;
        a[0] = g_Xfrag[addr];
        a[1] = g_Xfrag[addr + 16 * 32];   // mi=1 -> mtg+1
    };

    const int arow = (lane & 7) + ((lane >> 3) & 1) * 8;
    const int akc = lane >> 4;
    uint32_t baseB[4];
#pragma unroll
    for (int hg = 0; hg < 4; hg++) {
        const int row = warp_n * 64 + hg * 16 + arow;
        baseB[hg] = (uint32_t)(row * 128 + ((row & 7) << 4));
    }

    issueB(0, 0);
    uint4 a_cur[2], a_nxt[2];
    ldgA(0, 0, a_cur);

    for (int c = 0; c < 4; c++) {
        const int buf = c & 1;
        CP_WAIT0();
        __syncthreads();
        if (c < 3) issueB(c + 1, buf ^ 1);
        const uint32_t bb = smem_base + buf * STAGE2;
#pragma unroll
        for (int kk = 0; kk < 4; kk++) {
            const uint32_t kcx = (uint32_t)((kk * 2 + akc) << 4);
            uint32_t bq[4][4];
#pragma unroll
            for (int hg = 0; hg < 4; hg++)
                ldsm_x4(bq[hg], bb + (baseB[hg] ^ kcx));
            if (kk < 3)      ldgA(c, kk + 1, a_nxt);
            else if (c < 3)  ldgA(c + 1, 0, a_nxt);
#pragma unroll
            for (int mi = 0; mi < 2; mi++)
#pragma unroll
                for (int ni = 0; ni < 8; ni++) {
                    const int hg = ni >> 1, s2 = ni & 1;
                    mma_f16_u4(acc[mi * 8 + ni], a_cur[mi], bq[hg][s2], bq[hg][s2 + 2]);
                }
            a_cur[0] = a_nxt[0];
            a_cur[1] = a_nxt[1];
        }
    }

    // ---- epilogue: y = acc + D*u, direct ----
#pragma unroll
    for (int mi = 0; mi < 2; mi++) {
        const int r0 = m0 + warp_m * 32 + mi * 16 + (lane >> 2);
#pragma unroll
        for (int ni = 0; ni < 8; ni++) {
            const int gc = n0 + warp_n * 64 + ni * 8 + (lane & 3) * 2;
            const float d0 = __ldg(Dv + gc), d1 = __ldg(Dv + gc + 1);
            const float* a = acc[mi * 8 + ni];
            const float2 u0 = *reinterpret_cast<const float2*>(u + (size_t)r0 * 256 + gc);
            const float2 u1 = *reinterpret_cast<const float2*>(u + (size_t)(r0 + 8) * 256 + gc);
            *reinterpret_cast<float2*>(y + (size_t)r0 * 256 + gc) =
                make_float2(a[0] + d0 * u0.x, a[1] + d1 * u0.y);
            *reinterpret_cast<float2*>(y + (size_t)(r0 + 8) * 256 + gc) =
                make_float2(a[2] + d0 * u1.x, a[3] + d1 * u1.y);
        }
    }
}

// ---------------------------------------------------------------------------
extern "C" void kernel_launch(void* const* d_in, const int* in_sizes, int n_in,
                              void* d_out, int out_size) {
    const float* Lre     = (const float*)d_in[0];
    const float* Lim     = (const float*)d_in[1];
    const float* B       = (const float*)d_in[2];
    const float* C       = (const float*)d_in[3];
    const float* D       = (const float*)d_in[4];
    const float* logstep = (const float*)d_in[5];
    const float* u       = (const float*)d_in[6];
    float* y = (float*)d_out;

    cudaFuncSetAttribute(gemm1_kernel, cudaFuncAttributeMaxDynamicSharedMemorySize, SM_TOTAL1);
    cudaFuncSetAttribute(gemm2_kernel, cudaFuncAttributeMaxDynamicSharedMemorySize, SM_TOTAL2);

    prep_kernel<<<PDIM, HDIM>>>(Lre, Lim, B, C, logstep);

    dim3 grid(2, LSEQ / 64);
    gemm1_kernel<<<grid, NTHREADS, SM_TOTAL1>>>(u);
    carry_scan_par_kernel<<<PDIM, NCHUNK>>>();
    fix_frag_kernel<<<NCHUNK, 256>>>();
    gemm2_kernel<<<grid, NTHREADS, SM_TOTAL2>>>(u, y, D);
}